// round 15
// baseline (speedup 1.0000x reference)
#include <cuda_runtime.h>
#include <math.h>

#define BATCH  8
#define NPTS   131072
#define DIM    32
#define NLAB   33
#define KINST  32
#define CHUNK  256
#define CHUNKS (NPTS / CHUNK)        // 512 chunks per batch
#define BPB    111                   // blocks per batch
#define GRID   (BATCH * BPB)         // 888 = one wave at 6 blocks/SM
#define THREADS 256
#define NWARP   8
#define WPTS    (CHUNK / NWARP)      // 32 points per warp per chunk
#define ROWW   (KINST + 1)

// ---- scratch (no allocations). Zero at module load; k_final re-zeros its
// ---- batch slice every replay, so each graph replay starts clean.
__device__ float g_sums[BATCH * NLAB * DIM];
__device__ float g_counts[BATCH * NLAB];
__device__ float g_hinge[BATCH * NLAB];

// Pass 1 (persistent, one wave): per-(b,label) sums + counts. Block pinned to
// batch b, grid-strides over its chunks; SMEM accumulators zeroed/flushed
// ONCE per block. Warp-per-point lane-private RMW (race-free); 8-deep load
// groups; match_any counts. Block 0 zero-inits out[] for k_final's atomics.
__global__ void __launch_bounds__(THREADS) k_pass1(const float* __restrict__ emb,
                                                   const int* __restrict__ lab,
                                                   float* __restrict__ out) {
    __shared__ float s_sums[NWARP][NLAB * DIM];   // 33.8 KB
    __shared__ float s_cnt[NWARP][NLAB];
    int tid = threadIdx.x, wid = tid >> 5, lane = tid & 31;
    int b = blockIdx.x / BPB;
    int j = blockIdx.x % BPB;

    if (blockIdx.x == 0 && tid < 4) out[tid] = 0.f;   // reset output accums

    for (int i = tid; i < NWARP * NLAB * DIM; i += THREADS) (&s_sums[0][0])[i] = 0.f;
    for (int i = tid; i < NWARP * NLAB; i += THREADS)       (&s_cnt[0][0])[i]  = 0.f;
    __syncthreads();

    float* ws = s_sums[wid];
    float* wc = s_cnt[wid];
    int p0 = wid * WPTS;

    for (int c = j; c < CHUNKS; c += BPB) {
        const float* ebase = emb + ((size_t)b * NPTS + (size_t)c * CHUNK) * DIM;
        const int*   lbase = lab + (size_t)b * NPTS + (size_t)c * CHUNK;

        int myl = lbase[p0 + lane];                    // 32 labels, coalesced
        unsigned peers = __match_any_sync(0xffffffffu, myl);
        if ((__ffs(peers) - 1) == lane)                // one leader per label
            wc[myl] += (float)__popc(peers);           // distinct addrs: no race

        #pragma unroll
        for (int h = 0; h < 32; h += 8) {
            float v[8];
            #pragma unroll
            for (int i = 0; i < 8; i++)                // 8 LDGs in flight
                v[i] = ebase[(size_t)(p0 + h + i) * DIM + lane];
            #pragma unroll
            for (int i = 0; i < 8; i++) {
                int l = __shfl_sync(0xffffffffu, myl, h + i);
                ws[l * DIM + lane] += v[i];            // lane-private: no race
            }
        }
    }
    __syncthreads();

    for (int i = tid; i < NLAB * DIM; i += THREADS) {
        float s = 0.f;
        #pragma unroll
        for (int w = 0; w < NWARP; w++) s += s_sums[w][i];
        atomicAdd(&g_sums[b * NLAB * DIM + i], s);
    }
    for (int i = tid; i < NLAB; i += THREADS) {
        float s = 0.f;
        #pragma unroll
        for (int w = 0; w < NWARP; w++) s += s_cnt[w][i];
        atomicAdd(&g_counts[b * NLAB + i], s);
    }
}

// Pass 3 (persistent, one wave): hinge(||x - mean[label]|| - 0.1). Block
// pinned to batch b; means built once, hinge flushed once. Reversed chunk
// order (L2 reuse of pass1's tail). float4 quartets (8 lanes/point),
// 8 LDG.128 staged, 3-deep shfl reduce, group-private hinge replicas.
__global__ void __launch_bounds__(THREADS) k_pass3(const float* __restrict__ emb,
                                                   const int* __restrict__ lab) {
    __shared__ __align__(16) float s_mean[NLAB * DIM];
    __shared__ float s_h[NWARP * 4][NLAB];
    int tid = threadIdx.x, wid = tid >> 5, lane = tid & 31;
    int g = lane >> 3, s = lane & 7;
    int b = blockIdx.x / BPB;
    int j = blockIdx.x % BPB;

    for (int i = tid; i < NLAB * DIM; i += THREADS) {
        float c = g_counts[b * NLAB + i / DIM];
        s_mean[i] = g_sums[b * NLAB * DIM + i] / fmaxf(c, 1.f);
    }
    for (int i = tid; i < NWARP * 4 * NLAB; i += THREADS) (&s_h[0][0])[i] = 0.f;
    __syncthreads();

    const float4* m4 = (const float4*)s_mean;
    float* wh = s_h[wid * 4 + g];
    int p0 = wid * WPTS;

    for (int c = j; c < CHUNKS; c += BPB) {
        int chunk = (CHUNKS - 1) - c;                  // reversed within batch
        const float4* e4 = (const float4*)(emb + ((size_t)b * NPTS + (size_t)chunk * CHUNK) * DIM);
        const int*    lbase = lab + (size_t)b * NPTS + (size_t)chunk * CHUNK;

        int myl = lbase[p0 + lane];
        float4 v[8]; int lq[8];
        #pragma unroll
        for (int q = 0; q < 8; q++) {                  // 8 LDG.128 in flight
            int p = p0 + q * 4 + g;
            v[q] = e4[(size_t)p * 8 + s];              // 512B/warp contiguous
            lq[q] = __shfl_sync(0xffffffffu, myl, q * 4 + g);
        }
        #pragma unroll
        for (int q = 0; q < 8; q++) {
            float4 m = m4[lq[q] * 8 + s];
            float dx = v[q].x - m.x, dy = v[q].y - m.y;
            float dz = v[q].z - m.z, dw = v[q].w - m.w;
            float sq = dx * dx + dy * dy + dz * dz + dw * dw;
            sq += __shfl_xor_sync(0xffffffffu, sq, 1);
            sq += __shfl_xor_sync(0xffffffffu, sq, 2);
            sq += __shfl_xor_sync(0xffffffffu, sq, 4);
            if (s == 0) {
                float dist = sqrtf(sq + 1e-24f);
                wh[lq[q]] += fmaxf(dist - 0.1f, 0.f);  // group-private
            }
        }
    }
    __syncthreads();

    for (int i = tid; i < NLAB; i += THREADS) {
        float acc = 0.f;
        #pragma unroll
        for (int r = 0; r < NWARP * 4; r++) acc += s_h[r][i];
        atomicAdd(&g_hinge[b * NLAB + i], acc);
    }
}

// Finalize: grid=8, block b computes pull_b/push_b and atomically accumulates
// into out[] (pre-zeroed by pass1). Re-zeros its batch slice for next replay.
__global__ void __launch_bounds__(THREADS) k_final(float* __restrict__ out) {
    __shared__ __align__(16) float sm[DIM * ROWW];
    __shared__ float s_pres[KINST];
    __shared__ float s_hp[NWARP], s_pm[NWARP];
    int tid = threadIdx.x, wid = tid >> 5, lane = tid & 31;
    int b = blockIdx.x;

    #pragma unroll
    for (int i = 0; i < 4; i++) {
        int k = wid * 4 + i;
        float c = g_counts[b * NLAB + 1 + k];
        float m = g_sums[b * NLAB * DIM + (k + 1) * DIM + lane] / fmaxf(c, 1.f);
        sm[lane * ROWW + k] = m;                    // lane = dim
        if (lane == 0) s_pres[k] = (c > 0.f) ? 1.f : 0.f;
    }
    __syncthreads();

    if (wid == 0) {                                 // normalize: lane = instance
        float nrm = 0.f;
        #pragma unroll
        for (int d = 0; d < DIM; d++) { float x = sm[d * ROWW + lane]; nrm += x * x; }
        float rinv = 1.f / fmaxf(sqrtf(nrm), 1e-12f);
        #pragma unroll
        for (int d = 0; d < DIM; d++) sm[d * ROWW + lane] *= rinv;
    }
    __syncthreads();

    float pres = s_pres[lane];
    float mc[DIM];
    #pragma unroll
    for (int d = 0; d < DIM; d++) mc[d] = sm[d * ROWW + lane];

    float hp = 0.f, pm = 0.f;
    #pragma unroll
    for (int ii = 0; ii < 4; ii++) {
        int i = wid * 4 + ii;
        float pi = s_pres[i];
        float mask = (lane > i) ? pi * pres : 0.f;
        float sq = 0.f;
        #pragma unroll
        for (int d = 0; d < DIM; d++) {
            float diff = sm[d * ROWW + i] - mc[d];
            sq += diff * diff;
        }
        hp += fmaxf(1.0f - sqrtf(sq + 1e-24f), 0.f) * mask;  // 2*DELTA_D = 1
        pm += mask;
    }
    #pragma unroll
    for (int o = 16; o; o >>= 1) {
        hp += __shfl_xor_sync(0xffffffffu, hp, o);
        pm += __shfl_xor_sync(0xffffffffu, pm, o);
    }
    if (lane == 0) { s_hp[wid] = hp; s_pm[wid] = pm; }
    __syncthreads();

    if (wid == 0) {
        float c  = g_counts[b * NLAB + 1 + lane];
        float hs = g_hinge[b * NLAB + 1 + lane];
        float seg  = hs / fmaxf(c, 1.f);
        float pr   = (c > 0.f) ? 1.f : 0.f;
        float segsum = seg, ninst = pr;
        float hps = (lane < NWARP) ? s_hp[lane] : 0.f;
        float pms = (lane < NWARP) ? s_pm[lane] : 0.f;
        #pragma unroll
        for (int o = 16; o; o >>= 1) {
            segsum += __shfl_xor_sync(0xffffffffu, segsum, o);
            ninst  += __shfl_xor_sync(0xffffffffu, ninst, o);
            hps    += __shfl_xor_sync(0xffffffffu, hps, o);
            pms    += __shfl_xor_sync(0xffffffffu, pms, o);
        }
        if (lane == 0) {
            float pull_b = segsum / (ninst + 1e-6f) * (1.0f / BATCH);
            float push_b = ((ninst > 1.f) ? hps / (pms + 1e-6f) : 0.f) * (1.0f / BATCH);
            atomicAdd(&out[0], pull_b + push_b);
            atomicAdd(&out[1], pull_b);
            atomicAdd(&out[2], push_b);
        }
    }

    // re-zero this batch's accumulator slice for the next replay
    for (int i = tid; i < NLAB * DIM; i += THREADS) g_sums[b * NLAB * DIM + i] = 0.f;
    for (int i = tid; i < NLAB; i += THREADS) {
        g_counts[b * NLAB + i] = 0.f;
        g_hinge[b * NLAB + i]  = 0.f;
    }
}

extern "C" void kernel_launch(void* const* d_in, const int* in_sizes, int n_in,
                              void* d_out, int out_size) {
    const float* emb = (const float*)d_in[0];
    const int*   lab = (const int*)d_in[1];
    float* out = (float*)d_out;
    (void)in_sizes; (void)n_in; (void)out_size;

    k_pass1<<<GRID, THREADS>>>(emb, lab, out);
    k_pass3<<<GRID, THREADS>>>(emb, lab);
    k_final<<<BATCH, THREADS>>>(out);
}

// round 16
// speedup vs baseline: 1.1042x; 1.1042x over previous
#include <cuda_runtime.h>
#include <math.h>

#define BATCH  8
#define NPTS   131072
#define DIM    32
#define NLAB   33
#define KINST  32
#define CHUNK  512
#define CHUNKS (NPTS / CHUNK)        // 256 chunks per batch
#define NBLK   (BATCH * CHUNKS)      // 2048
#define THREADS 256
#define NWARP   8
#define WPTS    (CHUNK / NWARP)      // 64 points per warp
#define ROWW   (KINST + 1)

// ---- scratch (no allocations). Zero at module load; k_final re-zeros its
// ---- batch slice every replay, so each graph replay starts clean.
__device__ float g_sums[BATCH * NLAB * DIM];
__device__ float g_counts[BATCH * NLAB];
__device__ float g_hinge[BATCH * NLAB];

// Pass 1: per-(b,label) sums + counts. Warp-per-point lane-private SMEM RMW
// (race-free); 8-deep load groups; match_any counts. Block 0 zero-inits out[].
__global__ void __launch_bounds__(THREADS) k_pass1(const float* __restrict__ emb,
                                                   const int* __restrict__ lab,
                                                   float* __restrict__ out) {
    __shared__ float s_sums[NWARP][NLAB * DIM];
    __shared__ float s_cnt[NWARP][NLAB];
    int tid = threadIdx.x, wid = tid >> 5, lane = tid & 31;

    if (blockIdx.x == 0 && tid < 4) out[tid] = 0.f;   // reset output accums

    for (int i = tid; i < NWARP * NLAB * DIM; i += THREADS) (&s_sums[0][0])[i] = 0.f;
    for (int i = tid; i < NWARP * NLAB; i += THREADS)       (&s_cnt[0][0])[i]  = 0.f;
    __syncthreads();

    int b = blockIdx.x / CHUNKS;
    int chunk = blockIdx.x % CHUNKS;
    const float* ebase = emb + ((size_t)b * NPTS + (size_t)chunk * CHUNK) * DIM;
    const int*   lbase = lab + (size_t)b * NPTS + (size_t)chunk * CHUNK;

    float* ws = s_sums[wid];
    float* wc = s_cnt[wid];
    int p0 = wid * WPTS;

    int myl0 = lbase[p0 + lane];                    // labels for points 0..31
    int myl1 = lbase[p0 + 32 + lane];               // labels for points 32..63

    unsigned peers = __match_any_sync(0xffffffffu, myl0);
    if ((__ffs(peers) - 1) == lane) wc[myl0] += (float)__popc(peers);
    peers = __match_any_sync(0xffffffffu, myl1);
    if ((__ffs(peers) - 1) == lane) wc[myl1] += (float)__popc(peers);

    #pragma unroll
    for (int gix = 0; gix < 8; gix++) {             // 8 groups of 8 points
        float v[8];
        #pragma unroll
        for (int i = 0; i < 8; i++)                 // 8 LDGs batched in flight
            v[i] = ebase[(size_t)(p0 + gix * 8 + i) * DIM + lane];
        #pragma unroll
        for (int i = 0; i < 8; i++) {
            int pi = gix * 8 + i;
            int l = (pi < 32) ? __shfl_sync(0xffffffffu, myl0, pi)
                              : __shfl_sync(0xffffffffu, myl1, pi - 32);
            ws[l * DIM + lane] += v[i];             // lane-private: no race
        }
    }
    __syncthreads();

    for (int i = tid; i < NLAB * DIM; i += THREADS) {
        float s = 0.f;
        #pragma unroll
        for (int w = 0; w < NWARP; w++) s += s_sums[w][i];
        atomicAdd(&g_sums[b * NLAB * DIM + i], s);
    }
    for (int i = tid; i < NLAB; i += THREADS) {
        float s = 0.f;
        #pragma unroll
        for (int w = 0; w < NWARP; w++) s += s_cnt[w][i];
        atomicAdd(&g_counts[b * NLAB + i], s);
    }
}

// Pass 3: hinge(||x - mean[label]|| - 0.1). PDL: blocks launch during pass1's
// tail, zero s_h, THEN cudaGridDependencySynchronize() before reading pass1's
// outputs. Reversed block order (L2 reuse). float4 quartets, 8 LDG.128
// staged, 3-deep shfl reduce, group-private hinge replicas.
__global__ void __launch_bounds__(THREADS) k_pass3(const float* __restrict__ emb,
                                                   const int* __restrict__ lab) {
    __shared__ __align__(16) float s_mean[NLAB * DIM];
    __shared__ float s_h[NWARP * 4][NLAB];
    int tid = threadIdx.x, wid = tid >> 5, lane = tid & 31;
    int g = lane >> 3, s = lane & 7;

    int idx = NBLK - 1 - blockIdx.x;                // reversed for L2 reuse
    int b = idx / CHUNKS;
    int chunk = idx % CHUNKS;

    // pass1-independent preamble (overlaps pass1's tail under PDL)
    for (int i = tid; i < NWARP * 4 * NLAB; i += THREADS) (&s_h[0][0])[i] = 0.f;

    cudaGridDependencySynchronize();                // wait for pass1 results

    for (int i = tid; i < NLAB * DIM; i += THREADS) {
        float c = g_counts[b * NLAB + i / DIM];
        s_mean[i] = g_sums[b * NLAB * DIM + i] / fmaxf(c, 1.f);
    }
    __syncthreads();

    const float4* e4 = (const float4*)(emb + ((size_t)b * NPTS + (size_t)chunk * CHUNK) * DIM);
    const int*    lbase = lab + (size_t)b * NPTS + (size_t)chunk * CHUNK;
    const float4* m4 = (const float4*)s_mean;
    float* wh = s_h[wid * 4 + g];
    int p0 = wid * WPTS;

    for (int w = 0; w < WPTS; w += 32) {
        int myl = lbase[p0 + w + lane];
        float4 v[8]; int lq[8];
        #pragma unroll
        for (int q = 0; q < 8; q++) {               // 8 LDG.128 in flight
            int p = p0 + w + q * 4 + g;
            v[q] = e4[(size_t)p * 8 + s];           // 512B/warp contiguous
            lq[q] = __shfl_sync(0xffffffffu, myl, q * 4 + g);
        }
        #pragma unroll
        for (int q = 0; q < 8; q++) {
            float4 m = m4[lq[q] * 8 + s];
            float dx = v[q].x - m.x, dy = v[q].y - m.y;
            float dz = v[q].z - m.z, dw = v[q].w - m.w;
            float sq = dx * dx + dy * dy + dz * dz + dw * dw;
            sq += __shfl_xor_sync(0xffffffffu, sq, 1);
            sq += __shfl_xor_sync(0xffffffffu, sq, 2);
            sq += __shfl_xor_sync(0xffffffffu, sq, 4);
            if (s == 0) {
                float dist = sqrtf(sq + 1e-24f);
                wh[lq[q]] += fmaxf(dist - 0.1f, 0.f);
            }
        }
    }
    __syncthreads();

    for (int i = tid; i < NLAB; i += THREADS) {
        float acc = 0.f;
        #pragma unroll
        for (int r = 0; r < NWARP * 4; r++) acc += s_h[r][i];
        atomicAdd(&g_hinge[b * NLAB + i], acc);
    }
}

// Finalize: grid=8, block b computes pull_b/push_b and atomically accumulates
// into out[] (pre-zeroed by pass1). PDL: launch latency hidden under pass3;
// grid-dependency sync before any loads. Re-zeros its batch slice.
__global__ void __launch_bounds__(THREADS) k_final(float* __restrict__ out) {
    __shared__ __align__(16) float sm[DIM * ROWW];
    __shared__ float s_pres[KINST];
    __shared__ float s_hp[NWARP], s_pm[NWARP];
    int tid = threadIdx.x, wid = tid >> 5, lane = tid & 31;
    int b = blockIdx.x;

    cudaGridDependencySynchronize();                // wait for pass3 results

    #pragma unroll
    for (int i = 0; i < 4; i++) {
        int k = wid * 4 + i;
        float c = g_counts[b * NLAB + 1 + k];
        float m = g_sums[b * NLAB * DIM + (k + 1) * DIM + lane] / fmaxf(c, 1.f);
        sm[lane * ROWW + k] = m;                    // lane = dim
        if (lane == 0) s_pres[k] = (c > 0.f) ? 1.f : 0.f;
    }
    __syncthreads();

    if (wid == 0) {                                 // normalize: lane = instance
        float nrm = 0.f;
        #pragma unroll
        for (int d = 0; d < DIM; d++) { float x = sm[d * ROWW + lane]; nrm += x * x; }
        float rinv = 1.f / fmaxf(sqrtf(nrm), 1e-12f);
        #pragma unroll
        for (int d = 0; d < DIM; d++) sm[d * ROWW + lane] *= rinv;
    }
    __syncthreads();

    float pres = s_pres[lane];
    float mc[DIM];
    #pragma unroll
    for (int d = 0; d < DIM; d++) mc[d] = sm[d * ROWW + lane];

    float hp = 0.f, pm = 0.f;
    #pragma unroll
    for (int ii = 0; ii < 4; ii++) {
        int i = wid * 4 + ii;
        float pi = s_pres[i];
        float mask = (lane > i) ? pi * pres : 0.f;
        float sq = 0.f;
        #pragma unroll
        for (int d = 0; d < DIM; d++) {
            float diff = sm[d * ROWW + i] - mc[d];
            sq += diff * diff;
        }
        hp += fmaxf(1.0f - sqrtf(sq + 1e-24f), 0.f) * mask;  // 2*DELTA_D = 1
        pm += mask;
    }
    #pragma unroll
    for (int o = 16; o; o >>= 1) {
        hp += __shfl_xor_sync(0xffffffffu, hp, o);
        pm += __shfl_xor_sync(0xffffffffu, pm, o);
    }
    if (lane == 0) { s_hp[wid] = hp; s_pm[wid] = pm; }
    __syncthreads();

    if (wid == 0) {
        float c  = g_counts[b * NLAB + 1 + lane];
        float hs = g_hinge[b * NLAB + 1 + lane];
        float seg  = hs / fmaxf(c, 1.f);
        float pr   = (c > 0.f) ? 1.f : 0.f;
        float segsum = seg, ninst = pr;
        float hps = (lane < NWARP) ? s_hp[lane] : 0.f;
        float pms = (lane < NWARP) ? s_pm[lane] : 0.f;
        #pragma unroll
        for (int o = 16; o; o >>= 1) {
            segsum += __shfl_xor_sync(0xffffffffu, segsum, o);
            ninst  += __shfl_xor_sync(0xffffffffu, ninst, o);
            hps    += __shfl_xor_sync(0xffffffffu, hps, o);
            pms    += __shfl_xor_sync(0xffffffffu, pms, o);
        }
        if (lane == 0) {
            float pull_b = segsum / (ninst + 1e-6f) * (1.0f / BATCH);
            float push_b = ((ninst > 1.f) ? hps / (pms + 1e-6f) : 0.f) * (1.0f / BATCH);
            atomicAdd(&out[0], pull_b + push_b);
            atomicAdd(&out[1], pull_b);
            atomicAdd(&out[2], push_b);
        }
    }

    // re-zero this batch's accumulator slice for the next replay
    for (int i = tid; i < NLAB * DIM; i += THREADS) g_sums[b * NLAB * DIM + i] = 0.f;
    for (int i = tid; i < NLAB; i += THREADS) {
        g_counts[b * NLAB + i] = 0.f;
        g_hinge[b * NLAB + i]  = 0.f;
    }
}

extern "C" void kernel_launch(void* const* d_in, const int* in_sizes, int n_in,
                              void* d_out, int out_size) {
    const float* emb = (const float*)d_in[0];
    const int*   lab = (const int*)d_in[1];
    float* out = (float*)d_out;
    (void)in_sizes; (void)n_in; (void)out_size;

    k_pass1<<<NBLK, THREADS>>>(emb, lab, out);

    // PDL launches: overlap each kernel's preamble/launch latency with the
    // predecessor's tail; data deps guarded by cudaGridDependencySynchronize.
    cudaLaunchAttribute attr[1];
    attr[0].id = cudaLaunchAttributeProgrammaticStreamSerialization;
    attr[0].val.programmaticStreamSerializationAllowed = 1;

    cudaLaunchConfig_t cfg3 = {};
    cfg3.gridDim  = dim3(NBLK, 1, 1);
    cfg3.blockDim = dim3(THREADS, 1, 1);
    cfg3.attrs = attr;
    cfg3.numAttrs = 1;
    cudaLaunchKernelEx(&cfg3, k_pass3, emb, lab);

    cudaLaunchConfig_t cfgF = {};
    cfgF.gridDim  = dim3(BATCH, 1, 1);
    cfgF.blockDim = dim3(THREADS, 1, 1);
    cfgF.attrs = attr;
    cfgF.numAttrs = 1;
    cudaLaunchKernelEx(&cfgF, k_final, out);
}